// round 5
// baseline (speedup 1.0000x reference)
#include <cuda_runtime.h>

// 7-DOF forward kinematics. R5: 4 elements/thread register-blocked.
// 28 input floats = 7 aligned float4 loads; 24 output floats = 6 aligned
// float4 stores. Four independent MUFU+FMA chains per thread for ILP.

#define DEG 0.017453292519943295f

__device__ __forceinline__ void fk_one(
    float th0, float th1, float th2, float th3,
    float th4, float th5, float th6,
    float& px, float& py, float& pz,
    float& vx, float& vy, float& vz)
{
    float r0 = th0 * DEG;
    float r1 = th1 * DEG;
    float r2 = th2 * DEG;
    float r3 = th3 * DEG;
    float r4 = th4 * (-0.5f * DEG);
    float r5 = fmaf(th5, DEG / 4.5f, 10.0f * DEG);
    float r6 = fmaf(th6, DEG / 4.5f, 60.0f * DEG);

    float s0, c0, s1, c1, s2, c2, s3, c3, s4, c4, s5, c5, s6, c6;
    __sincosf(r0, &s0, &c0);
    __sincosf(r1, &s1, &c1);
    __sincosf(r2, &s2, &c2);
    __sincosf(r3, &s3, &c3);
    __sincosf(r4, &s4, &c4);
    __sincosf(r5, &s5, &c5);
    __sincosf(r6, &s6, &c6);

    px = 0.f; py = 0.f; pz = 0.f;
    vx = 0.f; vy = 0.f; vz = 1.f;

#define ROT_Z(c, s) do { \
        float _x = px, _y = py; px = (c)*_x - (s)*_y; py = (s)*_x + (c)*_y; \
        float _a = vx, _b = vy; vx = (c)*_a - (s)*_b; vy = (s)*_a + (c)*_b; \
    } while (0)
#define RY90() do { \
        float _x = px; px = pz; pz = -_x; \
        float _a = vx; vx = vz; vz = -_a; \
    } while (0)
#define RX90() do { \
        float _y = py; py = -pz; pz = _y; \
        float _b = vy; vy = -vz; vz = _b; \
    } while (0)
#define RXM90() do { \
        float _y = py; py = pz; pz = -_y; \
        float _b = vy; vy = vz; vz = -_b; \
    } while (0)

    // Chain right-to-left (T25 first); constant Rz's folded into (c,s) roles
    RY90();                                   // T25: Ry(90)
    px += 6.0f;                               // T24
    ROT_Z(c6, s6);                            // T23: Rz(a6)
    px += 6.0f; py += -1.0f;                  // T22,T21
    ROT_Z(s5, -c5);                           // T20,T19: Rz(a5-90)
    RXM90();                                  // T18
    pz += 10.0f;                              // T17
    ROT_Z(c4, s4);                            // T16: Rz(-th4/2)
    RY90();                                   // T15
    px += 10.0f;                              // T14
    ROT_Z(-c3, s3);                           // T13,T12: Rz(180-th3)
    RX90();                                   // T11
    px += 17.5f;                              // T10
    ROT_Z(c2, -s2);                           // T9: Rz(-th2)
    RXM90();                                  // T8
    px += 3.0f; pz += 9.5f;                   // T7
    ROT_Z(c1, s1);                            // T6
    RY90();                                   // T5
    py += -1.5f; pz += 2.5f;                  // T4
    ROT_Z(-s0, c0);                           // T3,T2: Rz(th0+90)
    py += 5.0f; pz += 19.5f;                  // T1

#undef ROT_Z
#undef RY90
#undef RX90
#undef RXM90
}

__global__ void __launch_bounds__(256) fk_kernel(
    const float* __restrict__ thetas,   // [B, 7]
    float* __restrict__ out,            // [B*3 points][B*3 vectors]
    int n)
{
    long long tidg = (long long)blockIdx.x * blockDim.x + threadIdx.x;
    long long e = tidg * 4;              // first of 4 elements
    if (e >= n) return;

    if ((e + 4 <= n) && ((n & 3) == 0)) {
        // --- fast path: fully vectorized ---
        const float4* g4 = (const float4*)(thetas + e * 7);
        float4 q0 = g4[0], q1 = g4[1], q2 = g4[2], q3 = g4[3];
        float4 q4 = g4[4], q5 = g4[5], q6 = g4[6];
        float in[28] = {
            q0.x, q0.y, q0.z, q0.w, q1.x, q1.y, q1.z,
            q1.w, q2.x, q2.y, q2.z, q2.w, q3.x, q3.y,
            q3.z, q3.w, q4.x, q4.y, q4.z, q4.w, q5.x,
            q5.y, q5.z, q5.w, q6.x, q6.y, q6.z, q6.w };

        float p[4][3], v[4][3];
        #pragma unroll
        for (int j = 0; j < 4; j++) {
            const float* t = in + j * 7;
            fk_one(t[0], t[1], t[2], t[3], t[4], t[5], t[6],
                   p[j][0], p[j][1], p[j][2], v[j][0], v[j][1], v[j][2]);
        }

        float4* gp = (float4*)(out + e * 3);
        gp[0] = make_float4(p[0][0], p[0][1], p[0][2], p[1][0]);
        gp[1] = make_float4(p[1][1], p[1][2], p[2][0], p[2][1]);
        gp[2] = make_float4(p[2][2], p[3][0], p[3][1], p[3][2]);
        float4* gv = (float4*)(out + (long long)n * 3 + e * 3);
        gv[0] = make_float4(v[0][0], v[0][1], v[0][2], v[1][0]);
        gv[1] = make_float4(v[1][1], v[1][2], v[2][0], v[2][1]);
        gv[2] = make_float4(v[2][2], v[3][0], v[3][1], v[3][2]);
    } else {
        // --- tail path: scalar per element ---
        for (int j = 0; j < 4; j++) {
            long long i = e + j;
            if (i >= n) break;
            const float* t = thetas + i * 7;
            float px, py, pz, vx, vy, vz;
            fk_one(t[0], t[1], t[2], t[3], t[4], t[5], t[6],
                   px, py, pz, vx, vy, vz);
            long long base = i * 3;
            out[base + 0] = px;
            out[base + 1] = py;
            out[base + 2] = pz;
            long long vbase = (long long)n * 3 + base;
            out[vbase + 0] = vx;
            out[vbase + 1] = vy;
            out[vbase + 2] = vz;
        }
    }
}

extern "C" void kernel_launch(void* const* d_in, const int* in_sizes, int n_in,
                              void* d_out, int out_size)
{
    const float* thetas = (const float*)d_in[0];
    float* out = (float*)d_out;
    int n = in_sizes[0] / 7;   // B
    int threads = 256;
    long long nthreads = ((long long)n + 3) / 4;
    int blocks = (int)((nthreads + threads - 1) / threads);
    fk_kernel<<<blocks, threads>>>(thetas, out, n);
}

// round 6
// speedup vs baseline: 1.0173x; 1.0173x over previous
#include <cuda_runtime.h>

// 7-DOF forward kinematics. R6: 4 elements/thread, fully register-resident
// (explicit scalar unpack of float4 loads - NO local arrays), 32-bit indexing.
// 7x LDG.128 in, 6x STG.128 out per 4 elements.

#define DEG 0.017453292519943295f

__device__ __forceinline__ void fk_one(
    float th0, float th1, float th2, float th3,
    float th4, float th5, float th6,
    float& px, float& py, float& pz,
    float& vx, float& vy, float& vz)
{
    float r0 = th0 * DEG;
    float r1 = th1 * DEG;
    float r2 = th2 * DEG;
    float r3 = th3 * DEG;
    float r4 = th4 * (-0.5f * DEG);
    float r5 = fmaf(th5, DEG / 4.5f, 10.0f * DEG);
    float r6 = fmaf(th6, DEG / 4.5f, 60.0f * DEG);

    float s0, c0, s1, c1, s2, c2, s3, c3, s4, c4, s5, c5, s6, c6;
    __sincosf(r0, &s0, &c0);
    __sincosf(r1, &s1, &c1);
    __sincosf(r2, &s2, &c2);
    __sincosf(r3, &s3, &c3);
    __sincosf(r4, &s4, &c4);
    __sincosf(r5, &s5, &c5);
    __sincosf(r6, &s6, &c6);

    px = 0.f; py = 0.f; pz = 0.f;
    vx = 0.f; vy = 0.f; vz = 1.f;

#define ROT_Z(c, s) do { \
        float _x = px, _y = py; px = (c)*_x - (s)*_y; py = (s)*_x + (c)*_y; \
        float _a = vx, _b = vy; vx = (c)*_a - (s)*_b; vy = (s)*_a + (c)*_b; \
    } while (0)
#define RY90() do { \
        float _x = px; px = pz; pz = -_x; \
        float _a = vx; vx = vz; vz = -_a; \
    } while (0)
#define RX90() do { \
        float _y = py; py = -pz; pz = _y; \
        float _b = vy; vy = -vz; vz = _b; \
    } while (0)
#define RXM90() do { \
        float _y = py; py = pz; pz = -_y; \
        float _b = vy; vy = vz; vz = -_b; \
    } while (0)

    RY90();                                   // T25: Ry(90)
    px += 6.0f;                               // T24
    ROT_Z(c6, s6);                            // T23: Rz(a6)
    px += 6.0f; py += -1.0f;                  // T22,T21
    ROT_Z(s5, -c5);                           // T20,T19: Rz(a5-90)
    RXM90();                                  // T18
    pz += 10.0f;                              // T17
    ROT_Z(c4, s4);                            // T16: Rz(-th4/2)
    RY90();                                   // T15
    px += 10.0f;                              // T14
    ROT_Z(-c3, s3);                           // T13,T12: Rz(180-th3)
    RX90();                                   // T11
    px += 17.5f;                              // T10
    ROT_Z(c2, -s2);                           // T9: Rz(-th2)
    RXM90();                                  // T8
    px += 3.0f; pz += 9.5f;                   // T7
    ROT_Z(c1, s1);                            // T6
    RY90();                                   // T5
    py += -1.5f; pz += 2.5f;                  // T4
    ROT_Z(-s0, c0);                           // T3,T2: Rz(th0+90)
    py += 5.0f; pz += 19.5f;                  // T1

#undef ROT_Z
#undef RY90
#undef RX90
#undef RXM90
}

__global__ void __launch_bounds__(256) fk_kernel(
    const float* __restrict__ thetas,   // [B, 7]
    float* __restrict__ out,            // [B*3 points][B*3 vectors]
    int n)
{
    int e = (blockIdx.x * 256 + threadIdx.x) * 4;   // first of 4 elements (32-bit)
    if (e >= n) return;

    if ((e + 4 <= n) && ((n & 3) == 0)) {
        const float4* g4 = (const float4*)(thetas + e * 7);
        float4 q0 = g4[0], q1 = g4[1], q2 = g4[2], q3 = g4[3];
        float4 q4 = g4[4], q5 = g4[5], q6 = g4[6];

        // Explicit scalar results (NO arrays -> stays in registers)
        float p0x, p0y, p0z, v0x, v0y, v0z;
        float p1x, p1y, p1z, v1x, v1y, v1z;
        float p2x, p2y, p2z, v2x, v2y, v2z;
        float p3x, p3y, p3z, v3x, v3y, v3z;

        fk_one(q0.x, q0.y, q0.z, q0.w, q1.x, q1.y, q1.z,
               p0x, p0y, p0z, v0x, v0y, v0z);
        fk_one(q1.w, q2.x, q2.y, q2.z, q2.w, q3.x, q3.y,
               p1x, p1y, p1z, v1x, v1y, v1z);
        fk_one(q3.z, q3.w, q4.x, q4.y, q4.z, q4.w, q5.x,
               p2x, p2y, p2z, v2x, v2y, v2z);
        fk_one(q5.y, q5.z, q5.w, q6.x, q6.y, q6.z, q6.w,
               p3x, p3y, p3z, v3x, v3y, v3z);

        float4* gp = (float4*)(out + e * 3);
        gp[0] = make_float4(p0x, p0y, p0z, p1x);
        gp[1] = make_float4(p1y, p1z, p2x, p2y);
        gp[2] = make_float4(p2z, p3x, p3y, p3z);
        float4* gv = (float4*)(out + n * 3 + e * 3);
        gv[0] = make_float4(v0x, v0y, v0z, v1x);
        gv[1] = make_float4(v1y, v1z, v2x, v2y);
        gv[2] = make_float4(v2z, v3x, v3y, v3z);
    } else {
        // tail: scalar per element
        for (int j = 0; j < 4; j++) {
            int i = e + j;
            if (i >= n) break;
            const float* t = thetas + i * 7;
            float px, py, pz, vx, vy, vz;
            fk_one(t[0], t[1], t[2], t[3], t[4], t[5], t[6],
                   px, py, pz, vx, vy, vz);
            int base = i * 3;
            out[base + 0] = px;
            out[base + 1] = py;
            out[base + 2] = pz;
            int vbase = n * 3 + base;
            out[vbase + 0] = vx;
            out[vbase + 1] = vy;
            out[vbase + 2] = vz;
        }
    }
}

extern "C" void kernel_launch(void* const* d_in, const int* in_sizes, int n_in,
                              void* d_out, int out_size)
{
    const float* thetas = (const float*)d_in[0];
    float* out = (float*)d_out;
    int n = in_sizes[0] / 7;   // B
    int threads = 256;
    int nthreads = (n + 3) / 4;
    int blocks = (nthreads + threads - 1) / threads;
    fk_kernel<<<blocks, threads>>>(thetas, out, n);
}

// round 7
// speedup vs baseline: 1.4060x; 1.3821x over previous
#include <cuda_runtime.h>

// 7-DOF forward kinematics. R7: back to the winning 1-elem/thread shape,
// with the transform chain hand-folded symbolically (zero-propagation +
// angle-sum collapse of the direction-vector chain) and 32-bit indexing.

#define DEG 0.017453292519943295f

__global__ void __launch_bounds__(256) fk_kernel(
    const float* __restrict__ thetas,   // [B, 7]
    float* __restrict__ out,            // [B*3 points][B*3 vectors]
    int n)
{
    int i = blockIdx.x * 256 + threadIdx.x;
    if (i >= n) return;

    const float* t = thetas + i * 7;
    float th0 = t[0], th1 = t[1], th2 = t[2], th3 = t[3];
    float th4 = t[4], th5 = t[5], th6 = t[6];

    float r0 = th0 * DEG;
    float r1 = th1 * DEG;
    float r2 = th2 * DEG;
    float r3 = th3 * DEG;
    float r4 = th4 * (-0.5f * DEG);
    float r5 = fmaf(th5, DEG / 4.5f, 10.0f * DEG);
    float r6 = fmaf(th6, DEG / 4.5f, 60.0f * DEG);

    float s0, c0, s1, c1, s2, c2, s3, c3, s4, c4, s5, c5, s6, c6;
    __sincosf(r0, &s0, &c0);
    __sincosf(r1, &s1, &c1);
    __sincosf(r2, &s2, &c2);
    __sincosf(r3, &s3, &c3);
    __sincosf(r4, &s4, &c4);
    __sincosf(r5, &s5, &c5);
    __sincosf(r6, &s6, &c6);

    // ---- hand-folded chain (verified against generic R2 chain) ----
    // after T25..T21: p=(A,Bq,0), v=(c6,s6,0)
    float A  = fmaf(6.f, c6, 6.f);
    float Bq = fmaf(6.f, s6, -1.f);
    // T20,T19 [ROT_Z(s5,-c5)]:
    float p5x = s5 * A + c5 * Bq;
    float p5y = s5 * Bq - c5 * A;
    float s56 = s5 * c6 + c5 * s6;   // sin(r5+r6)
    float c56 = c5 * c6 - s5 * s6;   // cos(r5+r6)
    // T18,T17,T16,T15,T14: p=(X,Y,Zp), v=(c56, s4*s56, -c4*s56)
    float X  = 20.f - p5y;
    float Y  = s4 * p5x;
    float vY = s4 * s56;
    // T13,T12 [ROT_Z(-c3,s3)]:
    float p11x = -c3 * X - s3 * Y;
    float p11y =  s3 * X - c3 * Y;
    float v11x = -c3 * c56 - s3 * vY;
    float v11y =  s3 * c56 - c3 * vY;
    // T11 [RX90] + T10:
    float p12y = c4 * p5x;
    float v12y = c4 * s56;
    float p13x = p11x + 17.5f;
    // T9 [ROT_Z(c2,-s2)]:
    float p14x = c2 * p13x + s2 * p12y;
    float p14y = c2 * p12y - s2 * p13x;
    float v14x = c2 * v11x + s2 * v12y;
    float v14y = c2 * v12y - s2 * v11x;
    // T8 [RXM90] + T7:
    float p16x = p14x + 3.f;
    float p16z = 9.5f - p14y;
    // T6 [ROT_Z(c1,s1)]:
    float p17x = c1 * p16x - s1 * p11y;
    float p17y = s1 * p16x + c1 * p11y;
    float v17x = c1 * v14x - s1 * v11y;
    float v17y = s1 * v14x + c1 * v11y;
    // T5 [RY90] + T4:
    float p19y = p17y - 1.5f;
    float p19z = 2.5f - p17x;
    // T3,T2 [ROT_Z(-s0,c0)] + T1:
    float px = -s0 * p16z - c0 * p19y;
    float py =  c0 * p16z - s0 * p19y + 5.f;
    float pz = p19z + 19.5f;
    float vx =  s0 * v14y - c0 * v17y;
    float vy = -c0 * v14y - s0 * v17y;
    float vz = -v17x;

    int base = i * 3;
    out[base + 0] = px;
    out[base + 1] = py;
    out[base + 2] = pz;
    int vbase = n * 3 + base;
    out[vbase + 0] = vx;
    out[vbase + 1] = vy;
    out[vbase + 2] = vz;
}

extern "C" void kernel_launch(void* const* d_in, const int* in_sizes, int n_in,
                              void* d_out, int out_size)
{
    const float* thetas = (const float*)d_in[0];
    float* out = (float*)d_out;
    int n = in_sizes[0] / 7;   // B
    int threads = 256;
    int blocks = (n + threads - 1) / threads;
    fk_kernel<<<blocks, threads>>>(thetas, out, n);
}